// round 16
// baseline (speedup 1.0000x reference)
#include <cuda_runtime.h>
#include <cuda_fp16.h>
#include <stdint.h>

#define MAX_NODES 100000
#define NIN 5
#define CAP 96   // max in-degree bucket capacity (lambda=32 Poisson; huge margin)

// Scratch (allocation-free rule: __device__ globals).
// Zero-initialized at load; k_aggr self-cleans g_cnt per replay.
__device__ __align__(16) uint4 g_msg16[MAX_NODES];       // fp16 {dis*a0..a4, dis, 0, 0}
__device__ __align__(16) int g_bucket[MAX_NODES * CAP];  // incoming src indices
__device__ float g_dis[MAX_NODES];
__device__ int g_cnt[MAX_NODES];   // in-degree (also place cursor)
__device__ int g_is32 = 0;  // dtype flag: set-only, dtype constant across replays

// ---------------- kernels ----------------

// Dtype detect: if int64, odd 32-bit words of edge_index are high halves of
// values in [0,1e5) -> all zero. If int32 they are node ids, mostly nonzero.
__global__ void k_detect(const unsigned int* __restrict__ buf) {
    int i = blockIdx.x * blockDim.x + threadIdx.x;   // 65536 threads, 512KB probe
    if (buf[2 * i + 1] != 0) g_is32 = 1;             // benign race, set-only
}

__device__ __forceinline__ int clampi(int v, int n) {
    return min(max(v, 0), n - 1);
}

// Bucket edges by target; cnt doubles as degree. 8 edges per thread ->
// 8 independent atomic->store chains in flight (place is latency-bound).
__global__ void k_place(const void* __restrict__ ei, int E, int n) {
    int t = blockIdx.x * blockDim.x + threadIdx.x;
    int e0 = t * 8;
    if (e0 >= E) return;
    int r[8], c[8];
    int m = min(8, E - e0);
    bool vec = (m == 8) && ((E & 3) == 0);  // vector path needs aligned E half
    if (vec) {
        if (g_is32) {
            const int* p = (const int*)ei;
            int4 rv0 = *(const int4*)(p + e0);
            int4 rv1 = *(const int4*)(p + e0 + 4);
            int4 cv0 = *(const int4*)(p + E + e0);
            int4 cv1 = *(const int4*)(p + E + e0 + 4);
            r[0] = rv0.x; r[1] = rv0.y; r[2] = rv0.z; r[3] = rv0.w;
            r[4] = rv1.x; r[5] = rv1.y; r[6] = rv1.z; r[7] = rv1.w;
            c[0] = cv0.x; c[1] = cv0.y; c[2] = cv0.z; c[3] = cv0.w;
            c[4] = cv1.x; c[5] = cv1.y; c[6] = cv1.z; c[7] = cv1.w;
        } else {
            const long long* p = (const long long*)ei;
#pragma unroll
            for (int i = 0; i < 4; i++) {
                longlong2 rv = *(const longlong2*)(p + e0 + 2 * i);
                longlong2 cv = *(const longlong2*)(p + E + e0 + 2 * i);
                r[2 * i] = (int)rv.x; r[2 * i + 1] = (int)rv.y;
                c[2 * i] = (int)cv.x; c[2 * i + 1] = (int)cv.y;
            }
        }
    } else {
        for (int i = 0; i < m; i++) {
            if (g_is32) {
                const int* p = (const int*)ei;
                r[i] = p[e0 + i]; c[i] = p[E + e0 + i];
            } else {
                const long long* p = (const long long*)ei;
                r[i] = (int)p[e0 + i]; c[i] = (int)p[E + e0 + i];
            }
        }
    }
#pragma unroll
    for (int i = 0; i < 8; i++) {
        if (i < m) {
            int col = clampi(c[i], n);
            int pos = atomicAdd(&g_cnt[col], 1);
            g_bucket[col * CAP + min(pos, CAP - 1)] = clampi(r[i], n);
        }
    }
}

// per node: dis = (cnt+1)^-1/2; msg16 = fp16{dis*atom[0..4], dis}
__global__ void k_pre(const float* __restrict__ atom, int n) {
    int i = blockIdx.x * blockDim.x + threadIdx.x;
    if (i >= n) return;
    float dis = rsqrtf((float)(g_cnt[i] + 1));  // +1 self loop
    g_dis[i] = dis;
    float a0 = atom[i * NIN + 0], a1 = atom[i * NIN + 1], a2 = atom[i * NIN + 2];
    float a3 = atom[i * NIN + 3], a4 = atom[i * NIN + 4];
    __half2 h0 = __floats2half2_rn(dis * a0, dis * a1);
    __half2 h1 = __floats2half2_rn(dis * a2, dis * a3);
    __half2 h2 = __floats2half2_rn(dis * a4, dis);
    uint4 m;
    m.x = *reinterpret_cast<unsigned int*>(&h0);
    m.y = *reinterpret_cast<unsigned int*>(&h1);
    m.z = *reinterpret_cast<unsigned int*>(&h2);
    m.w = 0;
    g_msg16[i] = m;
}

__device__ __forceinline__ void acc_msg(float* s, uint4 m) {
    float2 f0 = __half22float2(*reinterpret_cast<__half2*>(&m.x));
    float2 f1 = __half22float2(*reinterpret_cast<__half2*>(&m.y));
    float2 f2 = __half22float2(*reinterpret_cast<__half2*>(&m.z));
    s[0] += f0.x; s[1] += f0.y; s[2] += f1.x;
    s[3] += f1.y; s[4] += f2.x; s[5] += f2.y;
}

// Gather-aggregate + fused matvec epilogue. 8 lanes per node (half-warp-ish).
// Lane h handles bucket slots {4h..4h+3} mod 32: one int4 idx load -> 4
// independent 16B fp16 msg loads (1 L1 wavefront each).
// out[c] = relu(dis*(W@s[0..4]+s[5]*b)); sums include self (fp32).
__global__ __launch_bounds__(256, 6)
void k_aggr(const float* __restrict__ atom,
            const float* __restrict__ W,
            const float* __restrict__ b,
            float4* __restrict__ out4, int n) {
    int t = blockIdx.x * blockDim.x + threadIdx.x;
    int node = t >> 3;
    if (node >= n) return;
    int h = t & 7;   // lane within the node's 8-lane group

    const int* bp = &g_bucket[node * CAP];
    int cnt = min(g_cnt[node], CAP);

    float s[6] = {0.f, 0.f, 0.f, 0.f, 0.f, 0.f};
    int k = h * 4;
    for (; k + 3 < cnt; k += 32) {
        int4 idx = *reinterpret_cast<const int4*>(bp + k);  // 16B-aligned
        uint4 m0 = __ldg(&g_msg16[idx.x]);
        uint4 m1 = __ldg(&g_msg16[idx.y]);
        uint4 m2 = __ldg(&g_msg16[idx.z]);
        uint4 m3 = __ldg(&g_msg16[idx.w]);
        acc_msg(s, m0);
        acc_msg(s, m1);
        acc_msg(s, m2);
        acc_msg(s, m3);
    }
    // tail: remaining entries of this lane's final 4-slot group
    for (int kk = k; kk < min(k + 4, cnt); kk++)
        acc_msg(s, __ldg(&g_msg16[bp[kk]]));

    // reduce over the 8 lanes of this node (groups aligned within warp)
#pragma unroll
    for (int off = 1; off < 8; off <<= 1) {
#pragma unroll
        for (int i = 0; i < 6; i++)
            s[i] += __shfl_xor_sync(0xffffffff, s[i], off);
    }

    // self-loop term in fp32
    float dis = g_dis[node];
    if (h < 4) {
#pragma unroll
        for (int kk = 0; kk < NIN; kk++)
            s[kk] += dis * __ldg(&atom[node * NIN + kk]);
        float sb = s[5] + dis;

        // lanes 0..3 compute 4 output channels each
        int j0 = h << 2;
        float r[4];
#pragma unroll
        for (int jj = 0; jj < 4; jj++) {
            int j = j0 + jj;
            float y = sb * __ldg(&b[j]);
#pragma unroll
            for (int kk = 0; kk < NIN; kk++)
                y = fmaf(s[kk], __ldg(&W[j * NIN + kk]), y);
            r[jj] = fmaxf(y * dis, 0.0f);
        }
        out4[node * 4 + h] = make_float4(r[0], r[1], r[2], r[3]);
    } else if (h == 4) {
        // cleanup for next replay: all 8 lanes already read g_cnt (same warp)
        g_cnt[node] = 0;
    }
}

// ---------------- launch ----------------

extern "C" void kernel_launch(void* const* d_in, const int* in_sizes, int n_in,
                              void* d_out, int out_size) {
    // Identify inputs by element count (all distinct):
    //   atom: 500000 fp32 | edge_index: 6400000 (int32 OR int64)
    //   W: 80 fp32        | b: 16 fp32
    const float* atom = nullptr;
    const void* ei = nullptr;
    const float* W = nullptr;
    const float* b = nullptr;
    int n = MAX_NODES, E = 0;

    for (int i = 0; i < n_in; i++) {
        int sz = in_sizes[i];
        if (sz == 16) b = (const float*)d_in[i];
        else if (sz == 80) W = (const float*)d_in[i];
        else if (sz > 1000000) { ei = d_in[i]; E = sz / 2; }
        else { atom = (const float*)d_in[i]; n = sz / NIN; }
    }
    if (n > MAX_NODES) n = MAX_NODES;

    float* out = (float*)d_out;
    const int B = 256;
    k_detect<<<65536 / B, B>>>((const unsigned int*)ei);
    {
        int threads = (E + 7) / 8;
        k_place<<<(threads + B - 1) / B, B>>>(ei, E, n);
    }
    k_pre<<<(n + B - 1) / B, B>>>(atom, n);
    k_aggr<<<(n * 8 + B - 1) / B, B>>>(atom, W, b, (float4*)out, n);
}

// round 17
// speedup vs baseline: 1.0389x; 1.0389x over previous
#include <cuda_runtime.h>
#include <cuda_fp16.h>
#include <stdint.h>

#define MAX_NODES 100000
#define NIN 5
#define CAP 96   // max in-degree bucket capacity (lambda=32 Poisson; huge margin)

// Scratch (allocation-free rule: __device__ globals).
// Zero-initialized at load; k_aggr self-cleans g_cnt per replay.
__device__ __align__(16) uint4 g_msg16[MAX_NODES];       // fp16 {dis*a0..a4, dis, 0, 0}
__device__ __align__(16) int g_bucket[MAX_NODES * CAP];  // incoming src indices
__device__ float g_dis[MAX_NODES];
__device__ int g_cnt[MAX_NODES];   // in-degree (also place cursor)
__device__ int g_is32 = 0;  // dtype flag: set-only, dtype constant across replays

// ---------------- kernels ----------------

// Dtype detect: if int64, odd 32-bit words of edge_index are high halves of
// values in [0,1e5) -> all zero. If int32 they are node ids, mostly nonzero.
__global__ void k_detect(const unsigned int* __restrict__ buf) {
    int i = blockIdx.x * blockDim.x + threadIdx.x;   // 4096 threads
    int hit = 0;
#pragma unroll
    for (int r = 0; r < 16; r++)                     // 64K odd words probed
        hit |= (buf[2 * (i + r * 4096) + 1] != 0);
    if (hit) g_is32 = 1;                             // benign race, set-only
}

__device__ __forceinline__ int clampi(int v, int n) {
    return min(max(v, 0), n - 1);
}

// Bucket edges by target; cnt doubles as degree. 4 edges per thread,
// vector index loads, 4 independent return-atomic chains in flight.
__global__ void k_place(const void* __restrict__ ei, int E, int n) {
    int t = blockIdx.x * blockDim.x + threadIdx.x;
    int e0 = t * 4;
    if (e0 >= E) return;
    int r[4], c[4];
    int m = min(4, E - e0);
    if (m == 4) {
        if (g_is32) {
            const int* p = (const int*)ei;
            int4 rv = *(const int4*)(p + e0);
            int4 cv = *(const int4*)(p + E + e0);
            r[0] = rv.x; r[1] = rv.y; r[2] = rv.z; r[3] = rv.w;
            c[0] = cv.x; c[1] = cv.y; c[2] = cv.z; c[3] = cv.w;
        } else {
            const long long* p = (const long long*)ei;
            longlong2 rv0 = *(const longlong2*)(p + e0);
            longlong2 rv1 = *(const longlong2*)(p + e0 + 2);
            longlong2 cv0 = *(const longlong2*)(p + E + e0);
            longlong2 cv1 = *(const longlong2*)(p + E + e0 + 2);
            r[0] = (int)rv0.x; r[1] = (int)rv0.y; r[2] = (int)rv1.x; r[3] = (int)rv1.y;
            c[0] = (int)cv0.x; c[1] = (int)cv0.y; c[2] = (int)cv1.x; c[3] = (int)cv1.y;
        }
    } else {
        for (int i = 0; i < m; i++) {
            if (g_is32) {
                const int* p = (const int*)ei;
                r[i] = p[e0 + i]; c[i] = p[E + e0 + i];
            } else {
                const long long* p = (const long long*)ei;
                r[i] = (int)p[e0 + i]; c[i] = (int)p[E + e0 + i];
            }
        }
    }
#pragma unroll
    for (int i = 0; i < 4; i++) {
        if (i < m) {
            int col = clampi(c[i], n);
            int pos = atomicAdd(&g_cnt[col], 1);
            g_bucket[col * CAP + min(pos, CAP - 1)] = clampi(r[i], n);
        }
    }
}

// per node: dis = (cnt+1)^-1/2; msg16 = fp16{dis*atom[0..4], dis}
__global__ void k_pre(const float* __restrict__ atom, int n) {
    int i = blockIdx.x * blockDim.x + threadIdx.x;
    if (i >= n) return;
    float dis = rsqrtf((float)(g_cnt[i] + 1));  // +1 self loop
    g_dis[i] = dis;
    float a0 = atom[i * NIN + 0], a1 = atom[i * NIN + 1], a2 = atom[i * NIN + 2];
    float a3 = atom[i * NIN + 3], a4 = atom[i * NIN + 4];
    __half2 h0 = __floats2half2_rn(dis * a0, dis * a1);
    __half2 h1 = __floats2half2_rn(dis * a2, dis * a3);
    __half2 h2 = __floats2half2_rn(dis * a4, dis);
    uint4 m;
    m.x = *reinterpret_cast<unsigned int*>(&h0);
    m.y = *reinterpret_cast<unsigned int*>(&h1);
    m.z = *reinterpret_cast<unsigned int*>(&h2);
    m.w = 0;
    g_msg16[i] = m;
}

__device__ __forceinline__ void acc_msg(float* s, uint4 m) {
    float2 f0 = __half22float2(*reinterpret_cast<__half2*>(&m.x));
    float2 f1 = __half22float2(*reinterpret_cast<__half2*>(&m.y));
    float2 f2 = __half22float2(*reinterpret_cast<__half2*>(&m.z));
    s[0] += f0.x; s[1] += f0.y; s[2] += f1.x;
    s[3] += f1.y; s[4] += f2.x; s[5] += f2.y;
}

// Gather-aggregate + fused matvec epilogue. 4 lanes per node (same warp).
// Lane q handles bucket slots {4q..4q+3} mod 16: one int4 idx load -> 4
// independent 16B fp16 msg loads (1 L1 wavefront each).
// out[c] = relu(dis*(W@s[0..4]+s[5]*b)); sums include self (fp32).
// launch_bounds(256,8): cap regs at 32 -> 100% occupancy (R15 had 40 regs,
// 75% occ, and aggr was occupancy/latency limited).
__global__ __launch_bounds__(256, 8)
void k_aggr(const float* __restrict__ atom,
            const float* __restrict__ W,
            const float* __restrict__ b,
            float4* __restrict__ out4, int n) {
    int t = blockIdx.x * blockDim.x + threadIdx.x;
    int node = t >> 2;
    if (node >= n) return;
    int q = t & 3;

    const int* bp = &g_bucket[node * CAP];
    int cnt = min(g_cnt[node], CAP);

    float s[6] = {0.f, 0.f, 0.f, 0.f, 0.f, 0.f};
    int k = q * 4;
    for (; k + 3 < cnt; k += 16) {
        int4 idx = *reinterpret_cast<const int4*>(bp + k);  // 16B-aligned
        // 2x2 msg accumulation: fewer live uint4 regs (occupancy), loads
        // still issued back-to-back within each pair.
        {
            uint4 m0 = __ldg(&g_msg16[idx.x]);
            uint4 m1 = __ldg(&g_msg16[idx.y]);
            acc_msg(s, m0);
            acc_msg(s, m1);
        }
        {
            uint4 m2 = __ldg(&g_msg16[idx.z]);
            uint4 m3 = __ldg(&g_msg16[idx.w]);
            acc_msg(s, m2);
            acc_msg(s, m3);
        }
    }
    // tail: remaining entries of this lane's final 4-slot group
    for (int kk = k; kk < min(k + 4, cnt); kk++)
        acc_msg(s, __ldg(&g_msg16[bp[kk]]));

    // reduce over the 4 lanes of this node (lane groups aligned within warp)
#pragma unroll
    for (int off = 1; off < 4; off <<= 1) {
#pragma unroll
        for (int i = 0; i < 6; i++)
            s[i] += __shfl_xor_sync(0xffffffff, s[i], off);
    }

    // self-loop term in fp32
    float dis = g_dis[node];
#pragma unroll
    for (int kk = 0; kk < NIN; kk++)
        s[kk] += dis * __ldg(&atom[node * NIN + kk]);
    float sb = s[5] + dis;

    // each lane computes its 4 output channels
    int j0 = q << 2;
    float r[4];
#pragma unroll
    for (int jj = 0; jj < 4; jj++) {
        int j = j0 + jj;
        float y = sb * __ldg(&b[j]);
#pragma unroll
        for (int kk = 0; kk < NIN; kk++)
            y = fmaf(s[kk], __ldg(&W[j * NIN + kk]), y);
        r[jj] = fmaxf(y * dis, 0.0f);
    }
    out4[node * 4 + q] = make_float4(r[0], r[1], r[2], r[3]);

    // cleanup for next replay (all lanes of this node already read g_cnt;
    // same warp, so this store cannot precede their reads)
    if (q == 0) g_cnt[node] = 0;
}

// ---------------- launch ----------------

extern "C" void kernel_launch(void* const* d_in, const int* in_sizes, int n_in,
                              void* d_out, int out_size) {
    // Identify inputs by element count (all distinct):
    //   atom: 500000 fp32 | edge_index: 6400000 (int32 OR int64)
    //   W: 80 fp32        | b: 16 fp32
    const float* atom = nullptr;
    const void* ei = nullptr;
    const float* W = nullptr;
    const float* b = nullptr;
    int n = MAX_NODES, E = 0;

    for (int i = 0; i < n_in; i++) {
        int sz = in_sizes[i];
        if (sz == 16) b = (const float*)d_in[i];
        else if (sz == 80) W = (const float*)d_in[i];
        else if (sz > 1000000) { ei = d_in[i]; E = sz / 2; }
        else { atom = (const float*)d_in[i]; n = sz / NIN; }
    }
    if (n > MAX_NODES) n = MAX_NODES;

    float* out = (float*)d_out;
    const int B = 256;
    k_detect<<<16, B>>>((const unsigned int*)ei);
    {
        int threads = (E + 3) / 4;
        k_place<<<(threads + B - 1) / B, B>>>(ei, E, n);
    }
    k_pre<<<(n + B - 1) / B, B>>>(atom, n);
    k_aggr<<<(n * 4 + B - 1) / B, B>>>(atom, W, b, (float4*)out, n);
}